// round 10
// baseline (speedup 1.0000x reference)
#include <cuda_runtime.h>
#include <cuda_fp16.h>
#include <math.h>

#define N_NODES 50000
#define N_EDGES 800000
#define DIM     128
#define NHEAD   8

#define HS 136   // half stride: 272B == 16 (mod 128) -> ldmatrix conflict-free
#define RPAD 132 // float stride for LN result staging

// ---------------- scratch ----------------
__device__ __align__(16) __half g_hsrc[N_NODES * DIM];
__device__ __align__(16) __half g_hdst[N_NODES * DIM];
__device__ __align__(16) __half g_msg[N_NODES * DIM];
__device__ int g_cnt[N_NODES];        // histogram, then fill cursor (memset to 0)
__device__ int g_off[N_NODES + 1];    // CSR offsets by dst
__device__ int g_eid[N_EDGES];        // src node per CSR slot

__device__ __forceinline__ float lrelu(float v) { return fmaxf(v, 0.2f * v); }

__device__ __forceinline__ uint4 ldsm_x4(unsigned addr) {
    uint4 r;
    asm volatile("ldmatrix.sync.aligned.m8n8.x4.shared.b16 {%0,%1,%2,%3}, [%4];"
                 : "=r"(r.x), "=r"(r.y), "=r"(r.z), "=r"(r.w) : "r"(addr));
    return r;
}

__device__ __forceinline__ void mma_f16(float c[4], uint4 a, unsigned b0, unsigned b1) {
    asm volatile(
        "mma.sync.aligned.m16n8k16.row.col.f32.f16.f16.f32 "
        "{%0,%1,%2,%3},{%4,%5,%6,%7},{%8,%9},{%0,%1,%2,%3};"
        : "+f"(c[0]), "+f"(c[1]), "+f"(c[2]), "+f"(c[3])
        : "r"(a.x), "r"(a.y), "r"(a.z), "r"(a.w), "r"(b0), "r"(b1));
}

// ---------------- CSR build ----------------
__global__ void k_hist(const int* __restrict__ dst) {
    int e = blockIdx.x * blockDim.x + threadIdx.x;
    if (e < N_EDGES) atomicAdd(&g_cnt[dst[e]], 1);
}

// whole-array exclusive scan in ONE block (1024 threads x 49 elements)
__global__ void k_scan_all() {
    __shared__ int ws[32];
    const int tid = threadIdx.x;
    const int PER = (N_NODES + 1023) / 1024;  // 49
    int base = tid * PER;

    int local = 0;
#pragma unroll 7
    for (int i = 0; i < PER; i++) {
        int idx = base + i;
        if (idx < N_NODES) local += g_cnt[idx];
    }

    int lane = tid & 31, wid = tid >> 5;
    int v = local;
#pragma unroll
    for (int o = 1; o < 32; o <<= 1) {
        int n = __shfl_up_sync(0xFFFFFFFFu, v, o);
        if (lane >= o) v += n;
    }
    if (lane == 31) ws[wid] = v;
    __syncthreads();
    if (wid == 0) {
        int t = ws[lane];
#pragma unroll
        for (int o = 1; o < 32; o <<= 1) {
            int n = __shfl_up_sync(0xFFFFFFFFu, t, o);
            if (lane >= o) t += n;
        }
        ws[lane] = t;
    }
    __syncthreads();

    int run = (v - local) + (wid > 0 ? ws[wid - 1] : 0);  // exclusive prefix
#pragma unroll 7
    for (int i = 0; i < PER; i++) {
        int idx = base + i;
        if (idx < N_NODES) {
            int c = g_cnt[idx];
            g_off[idx] = run;
            g_cnt[idx] = run;  // fill cursor
            run += c;
        }
    }
    if (tid == 0) g_off[N_NODES] = N_EDGES;
}

__global__ void k_fill(const int* __restrict__ src, const int* __restrict__ dst) {
    int e = blockIdx.x * blockDim.x + threadIdx.x;
    if (e < N_EDGES) {
        int pos = atomicAdd(&g_cnt[dst[e]], 1);
        g_eid[pos] = src[e];
    }
}

// ---------------- shared GEMM helpers ----------------
// A fragments: xs (fp16, [.][HS]); B fragments: Wt (fp16 transposed [n][k], [.][HS])
// per-lane ldmatrix row mappings (computed once):
//   A x4: row = mbase + ((l>>3)&1)*8 + (l&7),  koff = (l>>4)*8
//   B x4: row = nbase + ((l>>4)&1)*8 + (l&7),  koff = ((l>>3)&1)*8

// ---------------- GEMM1 (fp16 HMMA): h = x @ W -> fp16, grid.y picks src/dst --------
__global__ void __launch_bounds__(256, 3)
k_gemm1(const float* __restrict__ x,
        const float* __restrict__ Wsrc, const float* __restrict__ Wdst) {
    extern __shared__ char smc[];
    __half* Wt = (__half*)smc;                 // [128 n][HS]
    __half* xs = (__half*)smc + 128 * HS;      // [64 m][HS]
    const int tid = threadIdx.x;

    const float* W = blockIdx.y ? Wdst : Wsrc;
    __half* hout   = blockIdx.y ? g_hdst : g_hsrc;

    // stage W transposed: Wt[n][k] = W[k][n]
    for (int i = tid; i < 128 * 32; i += 256) {
        int kk = i >> 5, n4 = (i & 31) << 2;
        float4 v = ((const float4*)W)[i];
        Wt[(n4 + 0) * HS + kk] = __float2half_rn(v.x);
        Wt[(n4 + 1) * HS + kk] = __float2half_rn(v.y);
        Wt[(n4 + 2) * HS + kk] = __float2half_rn(v.z);
        Wt[(n4 + 3) * HS + kk] = __float2half_rn(v.w);
    }
    __syncthreads();

    const int warp = tid >> 5, lane = tid & 31;
    const int m_off = (warp & 1) * 32;
    const int n_off = (warp >> 1) * 32;

    unsigned xs_base = (unsigned)__cvta_generic_to_shared(xs);
    unsigned wt_base = (unsigned)__cvta_generic_to_shared(Wt);

    unsigned adrA[2], adrB[2];
#pragma unroll
    for (int mt = 0; mt < 2; mt++) {
        int row = m_off + mt * 16 + ((lane >> 3) & 1) * 8 + (lane & 7);
        adrA[mt] = xs_base + (row * HS + (lane >> 4) * 8) * 2;
    }
#pragma unroll
    for (int jj = 0; jj < 2; jj++) {
        int row = n_off + jj * 16 + ((lane >> 4) & 1) * 8 + (lane & 7);
        adrB[jj] = wt_base + (row * HS + ((lane >> 3) & 1) * 8) * 2;
    }

    for (int r0 = blockIdx.x * 64; r0 < N_NODES; r0 += gridDim.x * 64) {
        __syncthreads();
        int rows = N_NODES - r0; if (rows > 64) rows = 64;
        for (int i = tid; i < rows * 32; i += 256) {
            int r = i >> 5, c4 = (i & 31) << 2;
            float4 v = ((const float4*)(x + (size_t)r0 * DIM))[i];
            __half2 h01 = __floats2half2_rn(v.x, v.y);
            __half2 h23 = __floats2half2_rn(v.z, v.w);
            *(uint2*)&xs[r * HS + c4] =
                make_uint2(*(unsigned*)&h01, *(unsigned*)&h23);
        }
        __syncthreads();

        float acc[2][4][4];
#pragma unroll
        for (int mt = 0; mt < 2; mt++)
#pragma unroll
            for (int j = 0; j < 4; j++)
#pragma unroll
                for (int c = 0; c < 4; c++) acc[mt][j][c] = 0.f;

#pragma unroll
        for (int kk = 0; kk < 8; kk++) {
            int kb = kk * 16 * 2;  // byte offset along k
            uint4 a0 = ldsm_x4(adrA[0] + kb);
            uint4 a1 = ldsm_x4(adrA[1] + kb);
            uint4 b0 = ldsm_x4(adrB[0] + kb);
            uint4 b1 = ldsm_x4(adrB[1] + kb);
            mma_f16(acc[0][0], a0, b0.x, b0.y);
            mma_f16(acc[0][1], a0, b0.z, b0.w);
            mma_f16(acc[0][2], a0, b1.x, b1.y);
            mma_f16(acc[0][3], a0, b1.z, b1.w);
            mma_f16(acc[1][0], a1, b0.x, b0.y);
            mma_f16(acc[1][1], a1, b0.z, b0.w);
            mma_f16(acc[1][2], a1, b1.x, b1.y);
            mma_f16(acc[1][3], a1, b1.z, b1.w);
        }

#pragma unroll
        for (int mt = 0; mt < 2; mt++) {
            int rl = m_off + mt * 16 + (lane >> 2);
#pragma unroll
            for (int j = 0; j < 4; j++) {
                int n = n_off + 8 * j + 2 * (lane & 3);
                if (rl < rows) {
                    __half2 h = __floats2half2_rn(acc[mt][j][0], acc[mt][j][1]);
                    *(__half2*)&hout[(size_t)(r0 + rl) * DIM + n] = h;
                }
                if (rl + 8 < rows) {
                    __half2 h = __floats2half2_rn(acc[mt][j][2], acc[mt][j][3]);
                    *(__half2*)&hout[(size_t)(r0 + rl + 8) * DIM + n] = h;
                }
            }
        }
    }
}

// ---------------- node-centric aggregate: one warp per dst node ----------------
__global__ void k_agg(const float* __restrict__ attn) {
    int node = (blockIdx.x * blockDim.x + threadIdx.x) >> 5;
    if (node >= N_NODES) return;
    int lane = threadIdx.x & 31;

    uint2 hdr = *(const uint2*)&g_hdst[(size_t)node * DIM + 4 * lane];
    float2 hd01 = __half22float2(*(__half2*)&hdr.x);
    float2 hd23 = __half22float2(*(__half2*)&hdr.y);
    float4 w = ((const float4*)attn)[lane];

    int beg = g_off[node], end = g_off[node + 1];
    float4 acc = make_float4(0.f, 0.f, 0.f, 0.f);
    float esum = 0.f;

    for (int base = beg; base < end; base += 32) {
        int n = end - base; if (n > 32) n = 32;
        int eid = (lane < n) ? g_eid[base + lane] : 0;

        int j = 0;
        for (; j + 2 <= n; j += 2) {
            int s0 = __shfl_sync(0xFFFFFFFFu, eid, j);
            int s1 = __shfl_sync(0xFFFFFFFFu, eid, j + 1);
            uint2 h0 = *(const uint2*)&g_hsrc[(size_t)s0 * DIM + 4 * lane];
            uint2 h1 = *(const uint2*)&g_hsrc[(size_t)s1 * DIM + 4 * lane];

            float2 a01 = __half22float2(*(__half2*)&h0.x);
            float2 a23 = __half22float2(*(__half2*)&h0.y);
            float p0 = lrelu(a01.x + hd01.x) * w.x + lrelu(a01.y + hd01.y) * w.y +
                       lrelu(a23.x + hd23.x) * w.z + lrelu(a23.y + hd23.y) * w.w;
            float2 b01 = __half22float2(*(__half2*)&h1.x);
            float2 b23 = __half22float2(*(__half2*)&h1.y);
            float p1 = lrelu(b01.x + hd01.x) * w.x + lrelu(b01.y + hd01.y) * w.y +
                       lrelu(b23.x + hd23.x) * w.z + lrelu(b23.y + hd23.y) * w.w;

            p0 += __shfl_xor_sync(0xFFFFFFFFu, p0, 1);
            p0 += __shfl_xor_sync(0xFFFFFFFFu, p0, 2);
            p1 += __shfl_xor_sync(0xFFFFFFFFu, p1, 1);
            p1 += __shfl_xor_sync(0xFFFFFFFFu, p1, 2);
            float e0 = __expf(p0), e1 = __expf(p1);

            acc.x += a01.x * e0 + b01.x * e1;
            acc.y += a01.y * e0 + b01.y * e1;
            acc.z += a23.x * e0 + b23.x * e1;
            acc.w += a23.y * e0 + b23.y * e1;
            esum += e0 + e1;
        }
        if (j < n) {
            int s0 = __shfl_sync(0xFFFFFFFFu, eid, j);
            uint2 h0 = *(const uint2*)&g_hsrc[(size_t)s0 * DIM + 4 * lane];
            float2 a01 = __half22float2(*(__half2*)&h0.x);
            float2 a23 = __half22float2(*(__half2*)&h0.y);
            float p0 = lrelu(a01.x + hd01.x) * w.x + lrelu(a01.y + hd01.y) * w.y +
                       lrelu(a23.x + hd23.x) * w.z + lrelu(a23.y + hd23.y) * w.w;
            p0 += __shfl_xor_sync(0xFFFFFFFFu, p0, 1);
            p0 += __shfl_xor_sync(0xFFFFFFFFu, p0, 2);
            float e0 = __expf(p0);
            acc.x += a01.x * e0; acc.y += a01.y * e0;
            acc.z += a23.x * e0; acc.w += a23.y * e0;
            esum += e0;
        }
    }

    float inv = 1.f / (esum + 1e-8f);
    __half2 m01 = __floats2half2_rn(acc.x * inv, acc.y * inv);
    __half2 m23 = __floats2half2_rn(acc.z * inv, acc.w * inv);
    *(uint2*)&g_msg[(size_t)node * DIM + 4 * lane] =
        make_uint2(*(unsigned*)&m01, *(unsigned*)&m23);
}

// ---------------- GEMM2 (fp16 HMMA) + bias + residual + LayerNorm ----------------
__global__ void __launch_bounds__(256, 2)
k_out(const float* __restrict__ Wout, const float* __restrict__ bias,
      const float* __restrict__ x, const float* __restrict__ gamma,
      const float* __restrict__ beta, float* __restrict__ out) {
    extern __shared__ char smc[];
    __half* Wt  = (__half*)smc;                          // [128 n][HS]
    __half* xs  = (__half*)smc + 128 * HS;               // [64 m][HS]
    float*  res = (float*)(smc + (128 + 64) * HS * 2);   // [64][RPAD]
    const int tid = threadIdx.x;

    for (int i = tid; i < 128 * 32; i += 256) {
        int kk = i >> 5, n4 = (i & 31) << 2;
        float4 v = ((const float4*)Wout)[i];
        Wt[(n4 + 0) * HS + kk] = __float2half_rn(v.x);
        Wt[(n4 + 1) * HS + kk] = __float2half_rn(v.y);
        Wt[(n4 + 2) * HS + kk] = __float2half_rn(v.z);
        Wt[(n4 + 3) * HS + kk] = __float2half_rn(v.w);
    }
    __syncthreads();

    const int warp = tid >> 5, lane = tid & 31;
    const int m_off = (warp & 1) * 32;
    const int n_off = (warp >> 1) * 32;

    unsigned xs_base = (unsigned)__cvta_generic_to_shared(xs);
    unsigned wt_base = (unsigned)__cvta_generic_to_shared(Wt);

    unsigned adrA[2], adrB[2];
#pragma unroll
    for (int mt = 0; mt < 2; mt++) {
        int row = m_off + mt * 16 + ((lane >> 3) & 1) * 8 + (lane & 7);
        adrA[mt] = xs_base + (row * HS + (lane >> 4) * 8) * 2;
    }
#pragma unroll
    for (int jj = 0; jj < 2; jj++) {
        int row = n_off + jj * 16 + ((lane >> 4) & 1) * 8 + (lane & 7);
        adrB[jj] = wt_base + (row * HS + ((lane >> 3) & 1) * 8) * 2;
    }

    for (int r0 = blockIdx.x * 64; r0 < N_NODES; r0 += gridDim.x * 64) {
        __syncthreads();
        int rows = N_NODES - r0; if (rows > 64) rows = 64;
        // stage messages (already fp16): raw 16B copies
        for (int i = tid; i < rows * 16; i += 256) {
            int r = i >> 4, c8 = (i & 15) << 3;
            uint4 v = *(const uint4*)&g_msg[(size_t)(r0 + r) * DIM + c8];
            *(uint4*)&xs[r * HS + c8] = v;
        }
        __syncthreads();

        float acc[2][4][4];
#pragma unroll
        for (int mt = 0; mt < 2; mt++)
#pragma unroll
            for (int j = 0; j < 4; j++)
#pragma unroll
                for (int c = 0; c < 4; c++) acc[mt][j][c] = 0.f;

#pragma unroll
        for (int kk = 0; kk < 8; kk++) {
            int kb = kk * 16 * 2;
            uint4 a0 = ldsm_x4(adrA[0] + kb);
            uint4 a1 = ldsm_x4(adrA[1] + kb);
            uint4 b0 = ldsm_x4(adrB[0] + kb);
            uint4 b1 = ldsm_x4(adrB[1] + kb);
            mma_f16(acc[0][0], a0, b0.x, b0.y);
            mma_f16(acc[0][1], a0, b0.z, b0.w);
            mma_f16(acc[0][2], a0, b1.x, b1.y);
            mma_f16(acc[0][3], a0, b1.z, b1.w);
            mma_f16(acc[1][0], a1, b0.x, b0.y);
            mma_f16(acc[1][1], a1, b0.z, b0.w);
            mma_f16(acc[1][2], a1, b1.x, b1.y);
            mma_f16(acc[1][3], a1, b1.z, b1.w);
        }

#pragma unroll
        for (int mt = 0; mt < 2; mt++) {
            int rl = m_off + mt * 16 + (lane >> 2);
#pragma unroll
            for (int j = 0; j < 4; j++) {
                int n = n_off + 8 * j + 2 * (lane & 3);
                res[rl * RPAD + n]           = acc[mt][j][0];
                res[rl * RPAD + n + 1]       = acc[mt][j][1];
                res[(rl + 8) * RPAD + n]     = acc[mt][j][2];
                res[(rl + 8) * RPAD + n + 1] = acc[mt][j][3];
            }
        }
        __syncthreads();

        // LN pass: 4 threads per row, 32 cols each
        {
            int row = tid >> 2, tr = tid & 3;
            if (row < rows) {
                size_t gr = (size_t)(r0 + row);
                float vals[8][4];
                float sum = 0.f, sq = 0.f;
#pragma unroll
                for (int c = 0; c < 8; c++) {
                    int col = tr * 32 + 4 * c;
                    float4 b4 = *((const float4*)&bias[col]);
                    float4 xr = *((const float4*)&x[gr * DIM + col]);
                    float* p = &res[row * RPAD + col];
                    float v0 = p[0] + b4.x + xr.x;
                    float v1 = p[1] + b4.y + xr.y;
                    float v2 = p[2] + b4.z + xr.z;
                    float v3 = p[3] + b4.w + xr.w;
                    vals[c][0] = v0; vals[c][1] = v1; vals[c][2] = v2; vals[c][3] = v3;
                    sum += v0 + v1 + v2 + v3;
                    sq  += v0 * v0 + v1 * v1 + v2 * v2 + v3 * v3;
                }
                sum += __shfl_xor_sync(0xFFFFFFFFu, sum, 1);
                sum += __shfl_xor_sync(0xFFFFFFFFu, sum, 2);
                sq  += __shfl_xor_sync(0xFFFFFFFFu, sq, 1);
                sq  += __shfl_xor_sync(0xFFFFFFFFu, sq, 2);
                float mean = sum * (1.f / 128.f);
                float var  = sq * (1.f / 128.f) - mean * mean;
                float rstd = rsqrtf(var + 1e-5f);
#pragma unroll
                for (int c = 0; c < 8; c++) {
                    int col = tr * 32 + 4 * c;
                    float4 g4  = *((const float4*)&gamma[col]);
                    float4 be4 = *((const float4*)&beta[col]);
                    float4 o4;
                    o4.x = (vals[c][0] - mean) * rstd * g4.x + be4.x;
                    o4.y = (vals[c][1] - mean) * rstd * g4.y + be4.y;
                    o4.z = (vals[c][2] - mean) * rstd * g4.z + be4.z;
                    o4.w = (vals[c][3] - mean) * rstd * g4.w + be4.w;
                    *((float4*)&out[gr * DIM + col]) = o4;
                }
            }
        }
        __syncthreads();  // res consumed before next tile overwrites
    }
}

// ---------------- launch ----------------
extern "C" void kernel_launch(void* const* d_in, const int* in_sizes, int n_in,
                              void* d_out, int out_size) {
    const float* x     = (const float*)d_in[0];
    const int*   ei    = (const int*)d_in[1];
    const float* Wsrc  = (const float*)d_in[2];
    const float* Wdst  = (const float*)d_in[3];
    const float* attn  = (const float*)d_in[4];
    const float* Wout  = (const float*)d_in[5];
    const float* bias  = (const float*)d_in[6];
    const float* gamma = (const float*)d_in[7];
    const float* beta  = (const float*)d_in[8];
    float* out = (float*)d_out;
    const int* src = ei;
    const int* dst = ei + N_EDGES;

    const int SMEM1 = (128 + 64) * HS * 2;               // 52224 B
    const int SMEM2 = SMEM1 + 64 * RPAD * 4;             // 86016 B

    cudaFuncSetAttribute(k_gemm1, cudaFuncAttributeMaxDynamicSharedMemorySize, SMEM1);
    cudaFuncSetAttribute(k_out,   cudaFuncAttributeMaxDynamicSharedMemorySize, SMEM2);

    const int EBLK = (N_EDGES + 255) / 256;

    // zero CSR counters (memset node, no extra kernel)
    void* p_cnt = nullptr;
    cudaGetSymbolAddress(&p_cnt, g_cnt);
    cudaMemsetAsync(p_cnt, 0, N_NODES * sizeof(int));

    // CSR build
    k_hist    <<<EBLK, 256>>>(dst);
    k_scan_all<<<1, 1024>>>();
    k_fill    <<<EBLK, 256>>>(src, dst);

    // node transforms -> fp16
    k_gemm1<<<dim3(148, 2), 256, SMEM1>>>(x, Wsrc, Wdst);

    // gather-aggregate (one warp per node)
    k_agg<<<(N_NODES * 32 + 255) / 256, 256>>>(attn);

    // output GEMM + residual + LN
    k_out<<<296, 256, SMEM2>>>(Wout, bias, x, gamma, beta, out);
}

// round 11
// speedup vs baseline: 1.0002x; 1.0002x over previous
#include <cuda_runtime.h>
#include <cuda_fp16.h>
#include <math.h>

#define N_NODES 50000
#define N_EDGES 800000
#define DIM     128
#define NHEAD   8

#define HS 136   // half stride: 272B == 16 (mod 128) -> ldmatrix conflict-free
#define RPAD 132 // float stride for LN result staging

// ---------------- scratch ----------------
__device__ __align__(16) __half g_hsrc[N_NODES * DIM];
__device__ __align__(16) __half g_hdst[N_NODES * DIM];
__device__ __align__(16) __half g_msg[N_NODES * DIM];
__device__ int g_cnt[N_NODES];        // histogram, then fill cursor (memset to 0)
__device__ int g_off[N_NODES + 1];    // CSR offsets by dst
__device__ int g_eid[N_EDGES];        // src node per CSR slot

__device__ __forceinline__ float lrelu(float v) { return fmaxf(v, 0.2f * v); }

__device__ __forceinline__ uint4 ldsm_x4(unsigned addr) {
    uint4 r;
    asm volatile("ldmatrix.sync.aligned.m8n8.x4.shared.b16 {%0,%1,%2,%3}, [%4];"
                 : "=r"(r.x), "=r"(r.y), "=r"(r.z), "=r"(r.w) : "r"(addr));
    return r;
}

__device__ __forceinline__ void mma_f16(float c[4], uint4 a, unsigned b0, unsigned b1) {
    asm volatile(
        "mma.sync.aligned.m16n8k16.row.col.f32.f16.f16.f32 "
        "{%0,%1,%2,%3},{%4,%5,%6,%7},{%8,%9},{%0,%1,%2,%3};"
        : "+f"(c[0]), "+f"(c[1]), "+f"(c[2]), "+f"(c[3])
        : "r"(a.x), "r"(a.y), "r"(a.z), "r"(a.w), "r"(b0), "r"(b1));
}

// ---------------- CSR build ----------------
__global__ void k_hist(const int* __restrict__ dst) {
    int e = blockIdx.x * blockDim.x + threadIdx.x;
    if (e < N_EDGES) atomicAdd(&g_cnt[dst[e]], 1);
}

// whole-array exclusive scan in ONE block (1024 threads x 49 elements)
__global__ void k_scan_all() {
    __shared__ int ws[32];
    const int tid = threadIdx.x;
    const int PER = (N_NODES + 1023) / 1024;  // 49
    int base = tid * PER;

    int local = 0;
#pragma unroll 7
    for (int i = 0; i < PER; i++) {
        int idx = base + i;
        if (idx < N_NODES) local += g_cnt[idx];
    }

    int lane = tid & 31, wid = tid >> 5;
    int v = local;
#pragma unroll
    for (int o = 1; o < 32; o <<= 1) {
        int n = __shfl_up_sync(0xFFFFFFFFu, v, o);
        if (lane >= o) v += n;
    }
    if (lane == 31) ws[wid] = v;
    __syncthreads();
    if (wid == 0) {
        int t = ws[lane];
#pragma unroll
        for (int o = 1; o < 32; o <<= 1) {
            int n = __shfl_up_sync(0xFFFFFFFFu, t, o);
            if (lane >= o) t += n;
        }
        ws[lane] = t;
    }
    __syncthreads();

    int run = (v - local) + (wid > 0 ? ws[wid - 1] : 0);  // exclusive prefix
#pragma unroll 7
    for (int i = 0; i < PER; i++) {
        int idx = base + i;
        if (idx < N_NODES) {
            int c = g_cnt[idx];
            g_off[idx] = run;
            g_cnt[idx] = run;  // fill cursor
            run += c;
        }
    }
    if (tid == 0) g_off[N_NODES] = N_EDGES;
}

__global__ void k_fill(const int* __restrict__ src, const int* __restrict__ dst) {
    int e = blockIdx.x * blockDim.x + threadIdx.x;
    if (e < N_EDGES) {
        int pos = atomicAdd(&g_cnt[dst[e]], 1);
        g_eid[pos] = src[e];
    }
}

// ---------------- shared GEMM helpers ----------------
// A fragments: xs (fp16, [.][HS]); B fragments: Wt (fp16 transposed [n][k], [.][HS])
// per-lane ldmatrix row mappings (computed once):
//   A x4: row = mbase + ((l>>3)&1)*8 + (l&7),  koff = (l>>4)*8
//   B x4: row = nbase + ((l>>4)&1)*8 + (l&7),  koff = ((l>>3)&1)*8

// ---------------- GEMM1 (fp16 HMMA): h = x @ W -> fp16, grid.y picks src/dst --------
__global__ void __launch_bounds__(256, 3)
k_gemm1(const float* __restrict__ x,
        const float* __restrict__ Wsrc, const float* __restrict__ Wdst) {
    extern __shared__ char smc[];
    __half* Wt = (__half*)smc;                 // [128 n][HS]
    __half* xs = (__half*)smc + 128 * HS;      // [64 m][HS]
    const int tid = threadIdx.x;

    const float* W = blockIdx.y ? Wdst : Wsrc;
    __half* hout   = blockIdx.y ? g_hdst : g_hsrc;

    // stage W transposed: Wt[n][k] = W[k][n]
    for (int i = tid; i < 128 * 32; i += 256) {
        int kk = i >> 5, n4 = (i & 31) << 2;
        float4 v = ((const float4*)W)[i];
        Wt[(n4 + 0) * HS + kk] = __float2half_rn(v.x);
        Wt[(n4 + 1) * HS + kk] = __float2half_rn(v.y);
        Wt[(n4 + 2) * HS + kk] = __float2half_rn(v.z);
        Wt[(n4 + 3) * HS + kk] = __float2half_rn(v.w);
    }
    __syncthreads();

    const int warp = tid >> 5, lane = tid & 31;
    const int m_off = (warp & 1) * 32;
    const int n_off = (warp >> 1) * 32;

    unsigned xs_base = (unsigned)__cvta_generic_to_shared(xs);
    unsigned wt_base = (unsigned)__cvta_generic_to_shared(Wt);

    unsigned adrA[2], adrB[2];
#pragma unroll
    for (int mt = 0; mt < 2; mt++) {
        int row = m_off + mt * 16 + ((lane >> 3) & 1) * 8 + (lane & 7);
        adrA[mt] = xs_base + (row * HS + (lane >> 4) * 8) * 2;
    }
#pragma unroll
    for (int jj = 0; jj < 2; jj++) {
        int row = n_off + jj * 16 + ((lane >> 4) & 1) * 8 + (lane & 7);
        adrB[jj] = wt_base + (row * HS + ((lane >> 3) & 1) * 8) * 2;
    }

    for (int r0 = blockIdx.x * 64; r0 < N_NODES; r0 += gridDim.x * 64) {
        __syncthreads();
        int rows = N_NODES - r0; if (rows > 64) rows = 64;
        for (int i = tid; i < rows * 32; i += 256) {
            int r = i >> 5, c4 = (i & 31) << 2;
            float4 v = ((const float4*)(x + (size_t)r0 * DIM))[i];
            __half2 h01 = __floats2half2_rn(v.x, v.y);
            __half2 h23 = __floats2half2_rn(v.z, v.w);
            *(uint2*)&xs[r * HS + c4] =
                make_uint2(*(unsigned*)&h01, *(unsigned*)&h23);
        }
        __syncthreads();

        float acc[2][4][4];
#pragma unroll
        for (int mt = 0; mt < 2; mt++)
#pragma unroll
            for (int j = 0; j < 4; j++)
#pragma unroll
                for (int c = 0; c < 4; c++) acc[mt][j][c] = 0.f;

#pragma unroll
        for (int kk = 0; kk < 8; kk++) {
            int kb = kk * 16 * 2;  // byte offset along k
            uint4 a0 = ldsm_x4(adrA[0] + kb);
            uint4 a1 = ldsm_x4(adrA[1] + kb);
            uint4 b0 = ldsm_x4(adrB[0] + kb);
            uint4 b1 = ldsm_x4(adrB[1] + kb);
            mma_f16(acc[0][0], a0, b0.x, b0.y);
            mma_f16(acc[0][1], a0, b0.z, b0.w);
            mma_f16(acc[0][2], a0, b1.x, b1.y);
            mma_f16(acc[0][3], a0, b1.z, b1.w);
            mma_f16(acc[1][0], a1, b0.x, b0.y);
            mma_f16(acc[1][1], a1, b0.z, b0.w);
            mma_f16(acc[1][2], a1, b1.x, b1.y);
            mma_f16(acc[1][3], a1, b1.z, b1.w);
        }

#pragma unroll
        for (int mt = 0; mt < 2; mt++) {
            int rl = m_off + mt * 16 + (lane >> 2);
#pragma unroll
            for (int j = 0; j < 4; j++) {
                int n = n_off + 8 * j + 2 * (lane & 3);
                if (rl < rows) {
                    __half2 h = __floats2half2_rn(acc[mt][j][0], acc[mt][j][1]);
                    *(__half2*)&hout[(size_t)(r0 + rl) * DIM + n] = h;
                }
                if (rl + 8 < rows) {
                    __half2 h = __floats2half2_rn(acc[mt][j][2], acc[mt][j][3]);
                    *(__half2*)&hout[(size_t)(r0 + rl + 8) * DIM + n] = h;
                }
            }
        }
    }
}

// ---------------- node-centric aggregate: one warp per dst node ----------------
__global__ void k_agg(const float* __restrict__ attn) {
    int node = (blockIdx.x * blockDim.x + threadIdx.x) >> 5;
    if (node >= N_NODES) return;
    int lane = threadIdx.x & 31;

    uint2 hdr = *(const uint2*)&g_hdst[(size_t)node * DIM + 4 * lane];
    float2 hd01 = __half22float2(*(__half2*)&hdr.x);
    float2 hd23 = __half22float2(*(__half2*)&hdr.y);
    float4 w = ((const float4*)attn)[lane];

    int beg = g_off[node], end = g_off[node + 1];
    float4 acc = make_float4(0.f, 0.f, 0.f, 0.f);
    float esum = 0.f;

    for (int base = beg; base < end; base += 32) {
        int n = end - base; if (n > 32) n = 32;
        int eid = (lane < n) ? g_eid[base + lane] : 0;

        int j = 0;
        for (; j + 2 <= n; j += 2) {
            int s0 = __shfl_sync(0xFFFFFFFFu, eid, j);
            int s1 = __shfl_sync(0xFFFFFFFFu, eid, j + 1);
            uint2 h0 = *(const uint2*)&g_hsrc[(size_t)s0 * DIM + 4 * lane];
            uint2 h1 = *(const uint2*)&g_hsrc[(size_t)s1 * DIM + 4 * lane];

            float2 a01 = __half22float2(*(__half2*)&h0.x);
            float2 a23 = __half22float2(*(__half2*)&h0.y);
            float p0 = lrelu(a01.x + hd01.x) * w.x + lrelu(a01.y + hd01.y) * w.y +
                       lrelu(a23.x + hd23.x) * w.z + lrelu(a23.y + hd23.y) * w.w;
            float2 b01 = __half22float2(*(__half2*)&h1.x);
            float2 b23 = __half22float2(*(__half2*)&h1.y);
            float p1 = lrelu(b01.x + hd01.x) * w.x + lrelu(b01.y + hd01.y) * w.y +
                       lrelu(b23.x + hd23.x) * w.z + lrelu(b23.y + hd23.y) * w.w;

            p0 += __shfl_xor_sync(0xFFFFFFFFu, p0, 1);
            p0 += __shfl_xor_sync(0xFFFFFFFFu, p0, 2);
            p1 += __shfl_xor_sync(0xFFFFFFFFu, p1, 1);
            p1 += __shfl_xor_sync(0xFFFFFFFFu, p1, 2);
            float e0 = __expf(p0), e1 = __expf(p1);

            acc.x += a01.x * e0 + b01.x * e1;
            acc.y += a01.y * e0 + b01.y * e1;
            acc.z += a23.x * e0 + b23.x * e1;
            acc.w += a23.y * e0 + b23.y * e1;
            esum += e0 + e1;
        }
        if (j < n) {
            int s0 = __shfl_sync(0xFFFFFFFFu, eid, j);
            uint2 h0 = *(const uint2*)&g_hsrc[(size_t)s0 * DIM + 4 * lane];
            float2 a01 = __half22float2(*(__half2*)&h0.x);
            float2 a23 = __half22float2(*(__half2*)&h0.y);
            float p0 = lrelu(a01.x + hd01.x) * w.x + lrelu(a01.y + hd01.y) * w.y +
                       lrelu(a23.x + hd23.x) * w.z + lrelu(a23.y + hd23.y) * w.w;
            p0 += __shfl_xor_sync(0xFFFFFFFFu, p0, 1);
            p0 += __shfl_xor_sync(0xFFFFFFFFu, p0, 2);
            float e0 = __expf(p0);
            acc.x += a01.x * e0; acc.y += a01.y * e0;
            acc.z += a23.x * e0; acc.w += a23.y * e0;
            esum += e0;
        }
    }

    float inv = 1.f / (esum + 1e-8f);
    __half2 m01 = __floats2half2_rn(acc.x * inv, acc.y * inv);
    __half2 m23 = __floats2half2_rn(acc.z * inv, acc.w * inv);
    *(uint2*)&g_msg[(size_t)node * DIM + 4 * lane] =
        make_uint2(*(unsigned*)&m01, *(unsigned*)&m23);
}

// ---------------- GEMM2 (fp16 HMMA) + bias + residual + LayerNorm ----------------
__global__ void __launch_bounds__(256, 2)
k_out(const float* __restrict__ Wout, const float* __restrict__ bias,
      const float* __restrict__ x, const float* __restrict__ gamma,
      const float* __restrict__ beta, float* __restrict__ out) {
    extern __shared__ char smc[];
    __half* Wt  = (__half*)smc;                          // [128 n][HS]
    __half* xs  = (__half*)smc + 128 * HS;               // [64 m][HS]
    float*  res = (float*)(smc + (128 + 64) * HS * 2);   // [64][RPAD]
    const int tid = threadIdx.x;

    for (int i = tid; i < 128 * 32; i += 256) {
        int kk = i >> 5, n4 = (i & 31) << 2;
        float4 v = ((const float4*)Wout)[i];
        Wt[(n4 + 0) * HS + kk] = __float2half_rn(v.x);
        Wt[(n4 + 1) * HS + kk] = __float2half_rn(v.y);
        Wt[(n4 + 2) * HS + kk] = __float2half_rn(v.z);
        Wt[(n4 + 3) * HS + kk] = __float2half_rn(v.w);
    }
    __syncthreads();

    const int warp = tid >> 5, lane = tid & 31;
    const int m_off = (warp & 1) * 32;
    const int n_off = (warp >> 1) * 32;

    unsigned xs_base = (unsigned)__cvta_generic_to_shared(xs);
    unsigned wt_base = (unsigned)__cvta_generic_to_shared(Wt);

    unsigned adrA[2], adrB[2];
#pragma unroll
    for (int mt = 0; mt < 2; mt++) {
        int row = m_off + mt * 16 + ((lane >> 3) & 1) * 8 + (lane & 7);
        adrA[mt] = xs_base + (row * HS + (lane >> 4) * 8) * 2;
    }
#pragma unroll
    for (int jj = 0; jj < 2; jj++) {
        int row = n_off + jj * 16 + ((lane >> 4) & 1) * 8 + (lane & 7);
        adrB[jj] = wt_base + (row * HS + ((lane >> 3) & 1) * 8) * 2;
    }

    for (int r0 = blockIdx.x * 64; r0 < N_NODES; r0 += gridDim.x * 64) {
        __syncthreads();
        int rows = N_NODES - r0; if (rows > 64) rows = 64;
        // stage messages (already fp16): raw 16B copies
        for (int i = tid; i < rows * 16; i += 256) {
            int r = i >> 4, c8 = (i & 15) << 3;
            uint4 v = *(const uint4*)&g_msg[(size_t)(r0 + r) * DIM + c8];
            *(uint4*)&xs[r * HS + c8] = v;
        }
        __syncthreads();

        float acc[2][4][4];
#pragma unroll
        for (int mt = 0; mt < 2; mt++)
#pragma unroll
            for (int j = 0; j < 4; j++)
#pragma unroll
                for (int c = 0; c < 4; c++) acc[mt][j][c] = 0.f;

#pragma unroll
        for (int kk = 0; kk < 8; kk++) {
            int kb = kk * 16 * 2;
            uint4 a0 = ldsm_x4(adrA[0] + kb);
            uint4 a1 = ldsm_x4(adrA[1] + kb);
            uint4 b0 = ldsm_x4(adrB[0] + kb);
            uint4 b1 = ldsm_x4(adrB[1] + kb);
            mma_f16(acc[0][0], a0, b0.x, b0.y);
            mma_f16(acc[0][1], a0, b0.z, b0.w);
            mma_f16(acc[0][2], a0, b1.x, b1.y);
            mma_f16(acc[0][3], a0, b1.z, b1.w);
            mma_f16(acc[1][0], a1, b0.x, b0.y);
            mma_f16(acc[1][1], a1, b0.z, b0.w);
            mma_f16(acc[1][2], a1, b1.x, b1.y);
            mma_f16(acc[1][3], a1, b1.z, b1.w);
        }

#pragma unroll
        for (int mt = 0; mt < 2; mt++) {
            int rl = m_off + mt * 16 + (lane >> 2);
#pragma unroll
            for (int j = 0; j < 4; j++) {
                int n = n_off + 8 * j + 2 * (lane & 3);
                res[rl * RPAD + n]           = acc[mt][j][0];
                res[rl * RPAD + n + 1]       = acc[mt][j][1];
                res[(rl + 8) * RPAD + n]     = acc[mt][j][2];
                res[(rl + 8) * RPAD + n + 1] = acc[mt][j][3];
            }
        }
        __syncthreads();

        // LN pass: 4 threads per row, 32 cols each
        {
            int row = tid >> 2, tr = tid & 3;
            if (row < rows) {
                size_t gr = (size_t)(r0 + row);
                float vals[8][4];
                float sum = 0.f, sq = 0.f;
#pragma unroll
                for (int c = 0; c < 8; c++) {
                    int col = tr * 32 + 4 * c;
                    float4 b4 = *((const float4*)&bias[col]);
                    float4 xr = *((const float4*)&x[gr * DIM + col]);
                    float* p = &res[row * RPAD + col];
                    float v0 = p[0] + b4.x + xr.x;
                    float v1 = p[1] + b4.y + xr.y;
                    float v2 = p[2] + b4.z + xr.z;
                    float v3 = p[3] + b4.w + xr.w;
                    vals[c][0] = v0; vals[c][1] = v1; vals[c][2] = v2; vals[c][3] = v3;
                    sum += v0 + v1 + v2 + v3;
                    sq  += v0 * v0 + v1 * v1 + v2 * v2 + v3 * v3;
                }
                sum += __shfl_xor_sync(0xFFFFFFFFu, sum, 1);
                sum += __shfl_xor_sync(0xFFFFFFFFu, sum, 2);
                sq  += __shfl_xor_sync(0xFFFFFFFFu, sq, 1);
                sq  += __shfl_xor_sync(0xFFFFFFFFu, sq, 2);
                float mean = sum * (1.f / 128.f);
                float var  = sq * (1.f / 128.f) - mean * mean;
                float rstd = rsqrtf(var + 1e-5f);
#pragma unroll
                for (int c = 0; c < 8; c++) {
                    int col = tr * 32 + 4 * c;
                    float4 g4  = *((const float4*)&gamma[col]);
                    float4 be4 = *((const float4*)&beta[col]);
                    float4 o4;
                    o4.x = (vals[c][0] - mean) * rstd * g4.x + be4.x;
                    o4.y = (vals[c][1] - mean) * rstd * g4.y + be4.y;
                    o4.z = (vals[c][2] - mean) * rstd * g4.z + be4.z;
                    o4.w = (vals[c][3] - mean) * rstd * g4.w + be4.w;
                    *((float4*)&out[gr * DIM + col]) = o4;
                }
            }
        }
        __syncthreads();  // res consumed before next tile overwrites
    }
}

// ---------------- launch ----------------
extern "C" void kernel_launch(void* const* d_in, const int* in_sizes, int n_in,
                              void* d_out, int out_size) {
    const float* x     = (const float*)d_in[0];
    const int*   ei    = (const int*)d_in[1];
    const float* Wsrc  = (const float*)d_in[2];
    const float* Wdst  = (const float*)d_in[3];
    const float* attn  = (const float*)d_in[4];
    const float* Wout  = (const float*)d_in[5];
    const float* bias  = (const float*)d_in[6];
    const float* gamma = (const float*)d_in[7];
    const float* beta  = (const float*)d_in[8];
    float* out = (float*)d_out;
    const int* src = ei;
    const int* dst = ei + N_EDGES;

    const int SMEM1 = (128 + 64) * HS * 2;               // 52224 B
    const int SMEM2 = SMEM1 + 64 * RPAD * 4;             // 86016 B

    cudaFuncSetAttribute(k_gemm1, cudaFuncAttributeMaxDynamicSharedMemorySize, SMEM1);
    cudaFuncSetAttribute(k_out,   cudaFuncAttributeMaxDynamicSharedMemorySize, SMEM2);

    const int EBLK = (N_EDGES + 255) / 256;

    // zero CSR counters (memset node, no extra kernel)
    void* p_cnt = nullptr;
    cudaGetSymbolAddress(&p_cnt, g_cnt);
    cudaMemsetAsync(p_cnt, 0, N_NODES * sizeof(int));

    // CSR build
    k_hist    <<<EBLK, 256>>>(dst);
    k_scan_all<<<1, 1024>>>();
    k_fill    <<<EBLK, 256>>>(src, dst);

    // node transforms -> fp16
    k_gemm1<<<dim3(148, 2), 256, SMEM1>>>(x, Wsrc, Wdst);

    // gather-aggregate (one warp per node)
    k_agg<<<(N_NODES * 32 + 255) / 256, 256>>>(attn);

    // output GEMM + residual + LN
    k_out<<<296, 256, SMEM2>>>(Wout, bias, x, gamma, beta, out);
}

// round 13
// speedup vs baseline: 1.0012x; 1.0011x over previous
#include <cuda_runtime.h>
#include <cuda_fp16.h>
#include <math.h>

#define N_NODES 50000
#define N_EDGES 800000
#define DIM     128
#define NHEAD   8

#define HS 136   // half stride: 272B == 16 (mod 128) -> ldmatrix conflict-free
#define RPAD 132 // float stride for LN result staging

// ---------------- scratch ----------------
__device__ __align__(16) __half g_hsrc[N_NODES * DIM];
__device__ __align__(16) __half g_hdst[N_NODES * DIM];
__device__ __align__(16) __half g_msg[N_NODES * DIM];
__device__ int g_cnt[N_NODES];        // histogram, then fill cursor (memset to 0)
__device__ int g_off[N_NODES + 1];    // CSR offsets by dst
__device__ int g_eid[N_EDGES];        // src node per CSR slot

__device__ __forceinline__ float lrelu(float v) { return fmaxf(v, 0.2f * v); }

__device__ __forceinline__ uint4 ldsm_x4(unsigned addr) {
    uint4 r;
    asm volatile("ldmatrix.sync.aligned.m8n8.x4.shared.b16 {%0,%1,%2,%3}, [%4];"
                 : "=r"(r.x), "=r"(r.y), "=r"(r.z), "=r"(r.w) : "r"(addr));
    return r;
}

__device__ __forceinline__ void mma_f16(float c[4], uint4 a, unsigned b0, unsigned b1) {
    asm volatile(
        "mma.sync.aligned.m16n8k16.row.col.f32.f16.f16.f32 "
        "{%0,%1,%2,%3},{%4,%5,%6,%7},{%8,%9},{%0,%1,%2,%3};"
        : "+f"(c[0]), "+f"(c[1]), "+f"(c[2]), "+f"(c[3])
        : "r"(a.x), "r"(a.y), "r"(a.z), "r"(a.w), "r"(b0), "r"(b1));
}

// ---------------- CSR build ----------------
__global__ void k_hist(const int* __restrict__ dst) {
    int e = blockIdx.x * blockDim.x + threadIdx.x;
    if (e < N_EDGES) atomicAdd(&g_cnt[dst[e]], 1);
}

// whole-array exclusive scan in ONE block (1024 threads x 49 elements)
__global__ void k_scan_all() {
    __shared__ int ws[32];
    const int tid = threadIdx.x;
    const int PER = (N_NODES + 1023) / 1024;  // 49
    int base = tid * PER;

    int local = 0;
#pragma unroll 7
    for (int i = 0; i < PER; i++) {
        int idx = base + i;
        if (idx < N_NODES) local += g_cnt[idx];
    }

    int lane = tid & 31, wid = tid >> 5;
    int v = local;
#pragma unroll
    for (int o = 1; o < 32; o <<= 1) {
        int n = __shfl_up_sync(0xFFFFFFFFu, v, o);
        if (lane >= o) v += n;
    }
    if (lane == 31) ws[wid] = v;
    __syncthreads();
    if (wid == 0) {
        int t = ws[lane];
#pragma unroll
        for (int o = 1; o < 32; o <<= 1) {
            int n = __shfl_up_sync(0xFFFFFFFFu, t, o);
            if (lane >= o) t += n;
        }
        ws[lane] = t;
    }
    __syncthreads();

    int run = (v - local) + (wid > 0 ? ws[wid - 1] : 0);  // exclusive prefix
#pragma unroll 7
    for (int i = 0; i < PER; i++) {
        int idx = base + i;
        if (idx < N_NODES) {
            int c = g_cnt[idx];
            g_off[idx] = run;
            g_cnt[idx] = run;  // fill cursor
            run += c;
        }
    }
    if (tid == 0) g_off[N_NODES] = N_EDGES;
}

__global__ void k_fill(const int* __restrict__ src, const int* __restrict__ dst) {
    int e = blockIdx.x * blockDim.x + threadIdx.x;
    if (e < N_EDGES) {
        int pos = atomicAdd(&g_cnt[dst[e]], 1);
        g_eid[pos] = src[e];
    }
}

// ---------------- shared GEMM helpers ----------------
// A fragments: xs (fp16, [.][HS]); B fragments: Wt (fp16 transposed [n][k], [.][HS])
// per-lane ldmatrix row mappings (computed once):
//   A x4: row = mbase + ((l>>3)&1)*8 + (l&7),  koff = (l>>4)*8
//   B x4: row = nbase + ((l>>4)&1)*8 + (l&7),  koff = ((l>>3)&1)*8

// ---------------- GEMM1 (fp16 HMMA): h = x @ W -> fp16, grid.y picks src/dst --------
__global__ void __launch_bounds__(256, 3)
k_gemm1(const float* __restrict__ x,
        const float* __restrict__ Wsrc, const float* __restrict__ Wdst) {
    extern __shared__ char smc[];
    __half* Wt = (__half*)smc;                 // [128 n][HS]
    __half* xs = (__half*)smc + 128 * HS;      // [64 m][HS]
    const int tid = threadIdx.x;

    const float* W = blockIdx.y ? Wdst : Wsrc;
    __half* hout   = blockIdx.y ? g_hdst : g_hsrc;

    // stage W transposed: Wt[n][k] = W[k][n]
    for (int i = tid; i < 128 * 32; i += 256) {
        int kk = i >> 5, n4 = (i & 31) << 2;
        float4 v = ((const float4*)W)[i];
        Wt[(n4 + 0) * HS + kk] = __float2half_rn(v.x);
        Wt[(n4 + 1) * HS + kk] = __float2half_rn(v.y);
        Wt[(n4 + 2) * HS + kk] = __float2half_rn(v.z);
        Wt[(n4 + 3) * HS + kk] = __float2half_rn(v.w);
    }
    __syncthreads();

    const int warp = tid >> 5, lane = tid & 31;
    const int m_off = (warp & 1) * 32;
    const int n_off = (warp >> 1) * 32;

    unsigned xs_base = (unsigned)__cvta_generic_to_shared(xs);
    unsigned wt_base = (unsigned)__cvta_generic_to_shared(Wt);

    unsigned adrA[2], adrB[2];
#pragma unroll
    for (int mt = 0; mt < 2; mt++) {
        int row = m_off + mt * 16 + ((lane >> 3) & 1) * 8 + (lane & 7);
        adrA[mt] = xs_base + (row * HS + (lane >> 4) * 8) * 2;
    }
#pragma unroll
    for (int jj = 0; jj < 2; jj++) {
        int row = n_off + jj * 16 + ((lane >> 4) & 1) * 8 + (lane & 7);
        adrB[jj] = wt_base + (row * HS + ((lane >> 3) & 1) * 8) * 2;
    }

    for (int r0 = blockIdx.x * 64; r0 < N_NODES; r0 += gridDim.x * 64) {
        __syncthreads();
        int rows = N_NODES - r0; if (rows > 64) rows = 64;
        for (int i = tid; i < rows * 32; i += 256) {
            int r = i >> 5, c4 = (i & 31) << 2;
            float4 v = ((const float4*)(x + (size_t)r0 * DIM))[i];
            __half2 h01 = __floats2half2_rn(v.x, v.y);
            __half2 h23 = __floats2half2_rn(v.z, v.w);
            *(uint2*)&xs[r * HS + c4] =
                make_uint2(*(unsigned*)&h01, *(unsigned*)&h23);
        }
        __syncthreads();

        float acc[2][4][4];
#pragma unroll
        for (int mt = 0; mt < 2; mt++)
#pragma unroll
            for (int j = 0; j < 4; j++)
#pragma unroll
                for (int c = 0; c < 4; c++) acc[mt][j][c] = 0.f;

#pragma unroll
        for (int kk = 0; kk < 8; kk++) {
            int kb = kk * 16 * 2;  // byte offset along k
            uint4 a0 = ldsm_x4(adrA[0] + kb);
            uint4 a1 = ldsm_x4(adrA[1] + kb);
            uint4 b0 = ldsm_x4(adrB[0] + kb);
            uint4 b1 = ldsm_x4(adrB[1] + kb);
            mma_f16(acc[0][0], a0, b0.x, b0.y);
            mma_f16(acc[0][1], a0, b0.z, b0.w);
            mma_f16(acc[0][2], a0, b1.x, b1.y);
            mma_f16(acc[0][3], a0, b1.z, b1.w);
            mma_f16(acc[1][0], a1, b0.x, b0.y);
            mma_f16(acc[1][1], a1, b0.z, b0.w);
            mma_f16(acc[1][2], a1, b1.x, b1.y);
            mma_f16(acc[1][3], a1, b1.z, b1.w);
        }

#pragma unroll
        for (int mt = 0; mt < 2; mt++) {
            int rl = m_off + mt * 16 + (lane >> 2);
#pragma unroll
            for (int j = 0; j < 4; j++) {
                int n = n_off + 8 * j + 2 * (lane & 3);
                if (rl < rows) {
                    __half2 h = __floats2half2_rn(acc[mt][j][0], acc[mt][j][1]);
                    *(__half2*)&hout[(size_t)(r0 + rl) * DIM + n] = h;
                }
                if (rl + 8 < rows) {
                    __half2 h = __floats2half2_rn(acc[mt][j][2], acc[mt][j][3]);
                    *(__half2*)&hout[(size_t)(r0 + rl + 8) * DIM + n] = h;
                }
            }
        }
    }
}

// ---------------- node-centric aggregate: one warp per dst node ----------------
__global__ void k_agg(const float* __restrict__ attn) {
    int node = (blockIdx.x * blockDim.x + threadIdx.x) >> 5;
    if (node >= N_NODES) return;
    int lane = threadIdx.x & 31;

    uint2 hdr = *(const uint2*)&g_hdst[(size_t)node * DIM + 4 * lane];
    float2 hd01 = __half22float2(*(__half2*)&hdr.x);
    float2 hd23 = __half22float2(*(__half2*)&hdr.y);
    float4 w = ((const float4*)attn)[lane];

    int beg = g_off[node], end = g_off[node + 1];
    float4 acc = make_float4(0.f, 0.f, 0.f, 0.f);
    float esum = 0.f;

    for (int base = beg; base < end; base += 32) {
        int n = end - base; if (n > 32) n = 32;
        int eid = (lane < n) ? g_eid[base + lane] : 0;

        int j = 0;
        for (; j + 2 <= n; j += 2) {
            int s0 = __shfl_sync(0xFFFFFFFFu, eid, j);
            int s1 = __shfl_sync(0xFFFFFFFFu, eid, j + 1);
            uint2 h0 = *(const uint2*)&g_hsrc[(size_t)s0 * DIM + 4 * lane];
            uint2 h1 = *(const uint2*)&g_hsrc[(size_t)s1 * DIM + 4 * lane];

            float2 a01 = __half22float2(*(__half2*)&h0.x);
            float2 a23 = __half22float2(*(__half2*)&h0.y);
            float p0 = lrelu(a01.x + hd01.x) * w.x + lrelu(a01.y + hd01.y) * w.y +
                       lrelu(a23.x + hd23.x) * w.z + lrelu(a23.y + hd23.y) * w.w;
            float2 b01 = __half22float2(*(__half2*)&h1.x);
            float2 b23 = __half22float2(*(__half2*)&h1.y);
            float p1 = lrelu(b01.x + hd01.x) * w.x + lrelu(b01.y + hd01.y) * w.y +
                       lrelu(b23.x + hd23.x) * w.z + lrelu(b23.y + hd23.y) * w.w;

            p0 += __shfl_xor_sync(0xFFFFFFFFu, p0, 1);
            p0 += __shfl_xor_sync(0xFFFFFFFFu, p0, 2);
            p1 += __shfl_xor_sync(0xFFFFFFFFu, p1, 1);
            p1 += __shfl_xor_sync(0xFFFFFFFFu, p1, 2);
            float e0 = __expf(p0), e1 = __expf(p1);

            acc.x += a01.x * e0 + b01.x * e1;
            acc.y += a01.y * e0 + b01.y * e1;
            acc.z += a23.x * e0 + b23.x * e1;
            acc.w += a23.y * e0 + b23.y * e1;
            esum += e0 + e1;
        }
        if (j < n) {
            int s0 = __shfl_sync(0xFFFFFFFFu, eid, j);
            uint2 h0 = *(const uint2*)&g_hsrc[(size_t)s0 * DIM + 4 * lane];
            float2 a01 = __half22float2(*(__half2*)&h0.x);
            float2 a23 = __half22float2(*(__half2*)&h0.y);
            float p0 = lrelu(a01.x + hd01.x) * w.x + lrelu(a01.y + hd01.y) * w.y +
                       lrelu(a23.x + hd23.x) * w.z + lrelu(a23.y + hd23.y) * w.w;
            p0 += __shfl_xor_sync(0xFFFFFFFFu, p0, 1);
            p0 += __shfl_xor_sync(0xFFFFFFFFu, p0, 2);
            float e0 = __expf(p0);
            acc.x += a01.x * e0; acc.y += a01.y * e0;
            acc.z += a23.x * e0; acc.w += a23.y * e0;
            esum += e0;
        }
    }

    float inv = 1.f / (esum + 1e-8f);
    __half2 m01 = __floats2half2_rn(acc.x * inv, acc.y * inv);
    __half2 m23 = __floats2half2_rn(acc.z * inv, acc.w * inv);
    *(uint2*)&g_msg[(size_t)node * DIM + 4 * lane] =
        make_uint2(*(unsigned*)&m01, *(unsigned*)&m23);
}

// ---------------- GEMM2 (fp16 HMMA) + bias + residual + LayerNorm ----------------
__global__ void __launch_bounds__(256, 2)
k_out(const float* __restrict__ Wout, const float* __restrict__ bias,
      const float* __restrict__ x, const float* __restrict__ gamma,
      const float* __restrict__ beta, float* __restrict__ out) {
    extern __shared__ char smc[];
    __half* Wt  = (__half*)smc;                          // [128 n][HS]
    __half* xs  = (__half*)smc + 128 * HS;               // [64 m][HS]
    float*  res = (float*)(smc + (128 + 64) * HS * 2);   // [64][RPAD]
    const int tid = threadIdx.x;

    for (int i = tid; i < 128 * 32; i += 256) {
        int kk = i >> 5, n4 = (i & 31) << 2;
        float4 v = ((const float4*)Wout)[i];
        Wt[(n4 + 0) * HS + kk] = __float2half_rn(v.x);
        Wt[(n4 + 1) * HS + kk] = __float2half_rn(v.y);
        Wt[(n4 + 2) * HS + kk] = __float2half_rn(v.z);
        Wt[(n4 + 3) * HS + kk] = __float2half_rn(v.w);
    }
    __syncthreads();

    const int warp = tid >> 5, lane = tid & 31;
    const int m_off = (warp & 1) * 32;
    const int n_off = (warp >> 1) * 32;

    unsigned xs_base = (unsigned)__cvta_generic_to_shared(xs);
    unsigned wt_base = (unsigned)__cvta_generic_to_shared(Wt);

    unsigned adrA[2], adrB[2];
#pragma unroll
    for (int mt = 0; mt < 2; mt++) {
        int row = m_off + mt * 16 + ((lane >> 3) & 1) * 8 + (lane & 7);
        adrA[mt] = xs_base + (row * HS + (lane >> 4) * 8) * 2;
    }
#pragma unroll
    for (int jj = 0; jj < 2; jj++) {
        int row = n_off + jj * 16 + ((lane >> 4) & 1) * 8 + (lane & 7);
        adrB[jj] = wt_base + (row * HS + ((lane >> 3) & 1) * 8) * 2;
    }

    for (int r0 = blockIdx.x * 64; r0 < N_NODES; r0 += gridDim.x * 64) {
        __syncthreads();
        int rows = N_NODES - r0; if (rows > 64) rows = 64;
        // stage messages (already fp16): raw 16B copies
        for (int i = tid; i < rows * 16; i += 256) {
            int r = i >> 4, c8 = (i & 15) << 3;
            uint4 v = *(const uint4*)&g_msg[(size_t)(r0 + r) * DIM + c8];
            *(uint4*)&xs[r * HS + c8] = v;
        }
        __syncthreads();

        float acc[2][4][4];
#pragma unroll
        for (int mt = 0; mt < 2; mt++)
#pragma unroll
            for (int j = 0; j < 4; j++)
#pragma unroll
                for (int c = 0; c < 4; c++) acc[mt][j][c] = 0.f;

#pragma unroll
        for (int kk = 0; kk < 8; kk++) {
            int kb = kk * 16 * 2;
            uint4 a0 = ldsm_x4(adrA[0] + kb);
            uint4 a1 = ldsm_x4(adrA[1] + kb);
            uint4 b0 = ldsm_x4(adrB[0] + kb);
            uint4 b1 = ldsm_x4(adrB[1] + kb);
            mma_f16(acc[0][0], a0, b0.x, b0.y);
            mma_f16(acc[0][1], a0, b0.z, b0.w);
            mma_f16(acc[0][2], a0, b1.x, b1.y);
            mma_f16(acc[0][3], a0, b1.z, b1.w);
            mma_f16(acc[1][0], a1, b0.x, b0.y);
            mma_f16(acc[1][1], a1, b0.z, b0.w);
            mma_f16(acc[1][2], a1, b1.x, b1.y);
            mma_f16(acc[1][3], a1, b1.z, b1.w);
        }

#pragma unroll
        for (int mt = 0; mt < 2; mt++) {
            int rl = m_off + mt * 16 + (lane >> 2);
#pragma unroll
            for (int j = 0; j < 4; j++) {
                int n = n_off + 8 * j + 2 * (lane & 3);
                res[rl * RPAD + n]           = acc[mt][j][0];
                res[rl * RPAD + n + 1]       = acc[mt][j][1];
                res[(rl + 8) * RPAD + n]     = acc[mt][j][2];
                res[(rl + 8) * RPAD + n + 1] = acc[mt][j][3];
            }
        }
        __syncthreads();

        // LN pass: 4 threads per row, 32 cols each
        {
            int row = tid >> 2, tr = tid & 3;
            if (row < rows) {
                size_t gr = (size_t)(r0 + row);
                float vals[8][4];
                float sum = 0.f, sq = 0.f;
#pragma unroll
                for (int c = 0; c < 8; c++) {
                    int col = tr * 32 + 4 * c;
                    float4 b4 = *((const float4*)&bias[col]);
                    float4 xr = *((const float4*)&x[gr * DIM + col]);
                    float* p = &res[row * RPAD + col];
                    float v0 = p[0] + b4.x + xr.x;
                    float v1 = p[1] + b4.y + xr.y;
                    float v2 = p[2] + b4.z + xr.z;
                    float v3 = p[3] + b4.w + xr.w;
                    vals[c][0] = v0; vals[c][1] = v1; vals[c][2] = v2; vals[c][3] = v3;
                    sum += v0 + v1 + v2 + v3;
                    sq  += v0 * v0 + v1 * v1 + v2 * v2 + v3 * v3;
                }
                sum += __shfl_xor_sync(0xFFFFFFFFu, sum, 1);
                sum += __shfl_xor_sync(0xFFFFFFFFu, sum, 2);
                sq  += __shfl_xor_sync(0xFFFFFFFFu, sq, 1);
                sq  += __shfl_xor_sync(0xFFFFFFFFu, sq, 2);
                float mean = sum * (1.f / 128.f);
                float var  = sq * (1.f / 128.f) - mean * mean;
                float rstd = rsqrtf(var + 1e-5f);
#pragma unroll
                for (int c = 0; c < 8; c++) {
                    int col = tr * 32 + 4 * c;
                    float4 g4  = *((const float4*)&gamma[col]);
                    float4 be4 = *((const float4*)&beta[col]);
                    float4 o4;
                    o4.x = (vals[c][0] - mean) * rstd * g4.x + be4.x;
                    o4.y = (vals[c][1] - mean) * rstd * g4.y + be4.y;
                    o4.z = (vals[c][2] - mean) * rstd * g4.z + be4.z;
                    o4.w = (vals[c][3] - mean) * rstd * g4.w + be4.w;
                    *((float4*)&out[gr * DIM + col]) = o4;
                }
            }
        }
        __syncthreads();  // res consumed before next tile overwrites
    }
}

// ---------------- launch ----------------
extern "C" void kernel_launch(void* const* d_in, const int* in_sizes, int n_in,
                              void* d_out, int out_size) {
    const float* x     = (const float*)d_in[0];
    const int*   ei    = (const int*)d_in[1];
    const float* Wsrc  = (const float*)d_in[2];
    const float* Wdst  = (const float*)d_in[3];
    const float* attn  = (const float*)d_in[4];
    const float* Wout  = (const float*)d_in[5];
    const float* bias  = (const float*)d_in[6];
    const float* gamma = (const float*)d_in[7];
    const float* beta  = (const float*)d_in[8];
    float* out = (float*)d_out;
    const int* src = ei;
    const int* dst = ei + N_EDGES;

    const int SMEM1 = (128 + 64) * HS * 2;               // 52224 B
    const int SMEM2 = SMEM1 + 64 * RPAD * 4;             // 86016 B

    cudaFuncSetAttribute(k_gemm1, cudaFuncAttributeMaxDynamicSharedMemorySize, SMEM1);
    cudaFuncSetAttribute(k_out,   cudaFuncAttributeMaxDynamicSharedMemorySize, SMEM2);

    const int EBLK = (N_EDGES + 255) / 256;

    // zero CSR counters (memset node, no extra kernel)
    void* p_cnt = nullptr;
    cudaGetSymbolAddress(&p_cnt, g_cnt);
    cudaMemsetAsync(p_cnt, 0, N_NODES * sizeof(int));

    // CSR build
    k_hist    <<<EBLK, 256>>>(dst);
    k_scan_all<<<1, 1024>>>();
    k_fill    <<<EBLK, 256>>>(src, dst);

    // node transforms -> fp16
    k_gemm1<<<dim3(148, 2), 256, SMEM1>>>(x, Wsrc, Wdst);

    // gather-aggregate (one warp per node)
    k_agg<<<(N_NODES * 32 + 255) / 256, 256>>>(attn);

    // output GEMM + residual + LN
    k_out<<<296, 256, SMEM2>>>(Wout, bias, x, gamma, beta, out);
}